// round 11
// baseline (speedup 1.0000x reference)
#include <cuda_runtime.h>
#include <cuda_bf16.h>
#include <math.h>

// Problem constants
#define CLOUDS 64
#define PPC    128      // points per cloud
#define DIM    128
#define NNODES (CLOUDS * PPC)   // 8192
#define EPSV   1e-5f

typedef unsigned long long ull;

// ---------------- scratch (device globals; no allocation allowed) -------------
__device__ float g_Ya[NNODES * DIM];    // X @ W1 (k-half 0)
__device__ float g_Yb[NNODES * DIM];    // X @ W1 (k-half 1)
__device__ float g_P2[NNODES * DIM];    // branch-2 pooled
__device__ float g_ps[128 * 128];       // per-CTA partial sums (batchnorm)
__device__ float g_pss[128 * 128];      // per-CTA partial sums of squares
__device__ float g_bstats[256];         // [0:128) scale, [128:256) shift
__device__ unsigned g_cnt;              // last-block ticket (reset each launch)

// ---------------- f32x2 / approx helpers --------------------------------------
__device__ __forceinline__ ull pack2(float lo, float hi) {
    ull r; asm("mov.b64 %0, {%1, %2};" : "=l"(r) : "f"(lo), "f"(hi)); return r;
}
__device__ __forceinline__ void unpack2(ull v, float& lo, float& hi) {
    asm("mov.b64 {%0, %1}, %2;" : "=f"(lo), "=f"(hi) : "l"(v));
}
__device__ __forceinline__ ull fma2(ull a, ull b, ull c) {
    ull d; asm("fma.rn.f32x2 %0, %1, %2, %3;" : "=l"(d) : "l"(a), "l"(b), "l"(c)); return d;
}
__device__ __forceinline__ ull add2(ull a, ull b) {
    ull d; asm("add.rn.f32x2 %0, %1, %2;" : "=l"(d) : "l"(a), "l"(b)); return d;
}
__device__ __forceinline__ float rsqrt_ap(float x) {
    float r; asm("rsqrt.approx.f32 %0, %1;" : "=f"(r) : "f"(x)); return r;
}
__device__ __forceinline__ float ex2_ap(float x) {
    float r; asm("ex2.approx.f32 %0, %1;" : "=f"(r) : "f"(x)); return r;
}

#define NEG1_2 0xBF800000BF800000ULL  // (-1.0f, -1.0f)
#define LOG2E  1.4426950408889634f

// ============================================================================
// K0: Y = X @ W1.  Register-blocked 8x8 tiles.
// Grid 128 = 64 row-blocks x 2 k-halves. CTA = 256 threads computes
// 128 rows x 128 cols over 64 k.  Thread (rg,cg) = rows rg*8..+8, colpairs
// cg*4..+4:  per k-iter 6 LDS.128 vs 32 FFMA2 (ratio 5.3) -> latency hidden
// by the FFMA2 stream.  smem 96 KB, 1 CTA/SM, 8 warps.
// ============================================================================
__global__ void __launch_bounds__(256, 1)
k0_gemm(const float* __restrict__ X, const float* __restrict__ W1) {
    extern __shared__ ull sm0[];
    ull* wp = sm0;            // [64 k][64 col-pairs]          (32 KB)
    ull* xd = sm0 + 4096;     // [64 k][128 rows] dup (v,v)    (64 KB)

    const int tid = threadIdx.x;
    const int r0  = (blockIdx.x >> 1) * 128;
    const int kb  = (blockIdx.x & 1) * 64;

    // W1 rows [kb, kb+64) -> smem (32 KB)
    const float4* w4 = (const float4*)W1 + kb * 32;
    float4* wps = (float4*)wp;
    #pragma unroll
    for (int t = 0; t < 8; t++) wps[tid + t * 256] = w4[tid + t * 256];

    // transpose + duplicate X block: xd[k*128 + r] = (x, x)
    #pragma unroll
    for (int t = 0; t < 32; t++) {
        int idx = tid + t * 256;      // 0..8191
        int r = idx & 127;
        int k = idx >> 7;
        float v = X[(r0 + r) * DIM + kb + k];
        xd[k * 128 + r] = pack2(v, v);
    }
    __syncthreads();

    const int rg = tid >> 4;   // 0..15  (rows rg*8..+8; 2-way bcast in warp)
    const int cg = tid & 15;   // 0..15  (colpairs cg*4..+4)

    ull acc[8][4];
    #pragma unroll
    for (int r = 0; r < 8; r++)
        #pragma unroll
        for (int c = 0; c < 4; c++) acc[r][c] = 0ULL;

    #pragma unroll 4
    for (int k = 0; k < 64; k++) {
        const ulonglong2* xv = (const ulonglong2*)(xd + k * 128 + rg * 8);
        ulonglong2 x0 = xv[0], x1 = xv[1], x2 = xv[2], x3 = xv[3];
        ull xr[8] = {x0.x, x0.y, x1.x, x1.y, x2.x, x2.y, x3.x, x3.y};
        const ulonglong2* wv2 = (const ulonglong2*)(wp + k * 64 + cg * 4);
        ulonglong2 wv0 = wv2[0], wv1 = wv2[1];
        ull wr[4] = {wv0.x, wv0.y, wv1.x, wv1.y};
        #pragma unroll
        for (int r = 0; r < 8; r++)
            #pragma unroll
            for (int c = 0; c < 4; c++)
                acc[r][c] = fma2(xr[r], wr[c], acc[r][c]);
    }

    float* dst = (blockIdx.x & 1) ? g_Yb : g_Ya;
    #pragma unroll
    for (int r = 0; r < 8; r++) {
        int row = r0 + rg * 8 + r;
        ull* o = (ull*)(dst + row * DIM);
        #pragma unroll
        for (int c = 0; c < 4; c++) o[cg * 4 + c] = acc[r][c];
    }
}

// ============================================================================
// K2: branch 2 (unchanged).  Writes g_P2 + BN partials; last CTA -> g_bstats.
// ============================================================================
#define ST_STRIDE 132
__global__ void __launch_bounds__(512, 1)
k2_branch2(const float* __restrict__ XYZ, const float* __restrict__ Wxyz,
           const float* __restrict__ bn_g, const float* __restrict__ bn_b) {
    extern __shared__ float sm2[];
    float* zs   = sm2;                       // [128][128]       (16384 f)
    float* st   = sm2 + 16384;               // [64][132] stage  (8448 f)
    float* xyzs = sm2 + 16384 + 8448;        // [128][4]         (512 f)
    float* wxs  = xyzs + 512;                // [3][128]         (384 f)

    const int tid  = threadIdx.x;
    const int w    = tid >> 5;
    const int lane = tid & 31;
    const int i_l   = ((w & 1) << 5) | lane;
    const int dbase = (w >> 1) << 4;

    const int cta   = blockIdx.x;
    const int node0 = (cta >> 1) << 7;
    const int i0    = (cta & 1) << 6;

    if (tid < 128) {
        const float* p = XYZ + (node0 + tid) * 3;
        xyzs[tid * 4 + 0] = p[0];
        xyzs[tid * 4 + 1] = p[1];
        xyzs[tid * 4 + 2] = p[2];
        xyzs[tid * 4 + 3] = 0.f;
    }
    if (tid < 384) wxs[tid] = Wxyz[tid];
    __syncthreads();

    #pragma unroll
    for (int t = 0; t < 32; t++) {
        int idx = tid + t * 512;
        int jn = idx >> 7;
        int d  = idx & 127;
        zs[idx] = xyzs[(jn << 2) + 0] * wxs[d]
                + xyzs[(jn << 2) + 1] * wxs[128 + d]
                + xyzs[(jn << 2) + 2] * wxs[256 + d];
    }
    __syncthreads();

    ull zi[8];
    {
        const ull* zsu = (const ull*)zs;
        int zoff = (((i0 + i_l) << 7) + dbase) >> 1;
        #pragma unroll
        for (int p = 0; p < 8; p++) zi[p] = zsu[zoff + p];
    }
    ull acc[8];
    #pragma unroll
    for (int p = 0; p < 8; p++) acc[p] = 0ULL;

    #pragma unroll 4
    for (int j = 0; j < 128; j++) {
        const ulonglong2* zj2 = (const ulonglong2*)(zs + (j << 7) + dbase);
        ulonglong2 a0 = zj2[0], a1 = zj2[1], a2 = zj2[2], a3 = zj2[3];
        ull zj[8] = {a0.x, a0.y, a1.x, a1.y, a2.x, a2.y, a3.x, a3.y};
        #pragma unroll
        for (int p = 0; p < 8; p++) {
            ull df = fma2(zj[p], NEG1_2, zi[p]);      // z_i - z_j
            float lo, hi;
            unpack2(df, lo, hi);
            lo = fmaxf(lo, 0.f);
            hi = fmaxf(hi, 0.f);
            acc[p] = add2(acc[p], pack2(lo, hi));
        }
    }

    float af[16];
    #pragma unroll
    for (int p = 0; p < 8; p++) unpack2(acc[p], af[2 * p], af[2 * p + 1]);
    #pragma unroll
    for (int q = 0; q < 4; q++) {
        float4 o;
        o.x = af[q * 4 + 0]; o.y = af[q * 4 + 1];
        o.z = af[q * 4 + 2]; o.w = af[q * 4 + 3];
        *(float4*)(st + i_l * ST_STRIDE + dbase + q * 4) = o;
    }
    __syncthreads();

    if (tid < 128) {
        float S = 0.f, SS = 0.f;
        #pragma unroll 8
        for (int i = 0; i < 64; i++) {
            float v = st[i * ST_STRIDE + tid];
            S += v; SS += v * v;
        }
        g_ps[cta * 128 + tid]  = S;
        g_pss[cta * 128 + tid] = SS;
    }
    const int nb = node0 + i0;
    #pragma unroll
    for (int t = 0; t < 16; t++) {
        int idx = tid + t * 512;     // 0 .. 8191
        int i = idx >> 7;
        int d = idx & 127;
        g_P2[((nb + i) << 7) + d] = st[i * ST_STRIDE + d];
    }

    // ---- last-block: reduce partials -> g_bstats (deterministic fixed order) ----
    __shared__ unsigned s_tk;
    __threadfence();
    if (tid == 0) s_tk = atomicAdd(&g_cnt, 1u);
    __syncthreads();
    if (s_tk == 127u) {
        __threadfence();
        const int d   = tid & 127;
        const int grp = tid >> 7;       // 0..3, 32 CTAs each
        const float* ps  = g_ps  + grp * 32 * 128 + d;
        const float* pss = g_pss + grp * 32 * 128 + d;
        float S = 0.f, SS = 0.f;
        #pragma unroll 8
        for (int c = 0; c < 32; c++) {
            S  += ps[c * 128];
            SS += pss[c * 128];
        }
        st[grp * 128 + d]       = S;     // reuse st
        st[512 + grp * 128 + d] = SS;
        __syncthreads();
        if (tid < 128) {
            float St  = st[tid] + st[128 + tid] + st[256 + tid] + st[384 + tid];
            float SSt = st[512 + tid] + st[640 + tid] + st[768 + tid] + st[896 + tid];
            float mu  = St * (1.f / (float)NNODES);
            float var = SSt * (1.f / (float)NNODES) - mu * mu;
            float inv = 1.f / sqrtf(var + EPSV);
            float scale = inv * bn_g[tid];
            g_bstats[tid]       = scale;
            g_bstats[128 + tid] = bn_b[tid] - mu * scale;
        }
        __threadfence();
        if (tid == 0) g_cnt = 0u;       // reset for next launch
    }
}

// ============================================================================
// K1: branch 1 + fused output (unchanged from R10).
// 1024 threads = 32 warps; warp = i-pair, lane = d-chunk of 4 floats.
// ============================================================================
__global__ void __launch_bounds__(1024, 1)
k1_branch1(const float* __restrict__ X, const float* __restrict__ XYZ,
           const float* __restrict__ b1, const float* __restrict__ ln_g,
           const float* __restrict__ ln_b, float* __restrict__ out) {
    extern __shared__ float sm1[];
    float* ys   = sm1;            // [128][128] Y of the cloud     (16384 f)
    float* ws   = sm1 + 16384;    // [128 j][64 i] edge weights     (8192 f)
    float* xyzs = sm1 + 24576;    // [128][4] xyz of the cloud      (512 f)

    const int tid  = threadIdx.x;
    const int w    = tid >> 5;        // 0..31  (i-pair index)
    const int lane = tid & 31;        // d-chunk
    const int iA   = w << 1;          // local i, even
    const int iB   = iA + 1;          // local i, odd
    const int dbase = lane << 2;      // 0..124 step 4

    const int cta   = blockIdx.x;
    const int node0 = (cta >> 1) << 7;   // cloud * 128
    const int i0    = (cta & 1) << 6;    // 0 or 64

    // load cloud Y = g_Ya + g_Yb
    {
        const float4* Ya = (const float4*)(g_Ya + node0 * DIM);
        const float4* Yb = (const float4*)(g_Yb + node0 * DIM);
        float4* ysv = (float4*)ys;
        #pragma unroll
        for (int t = 0; t < 4; t++) {
            int idx = tid + t * 1024;
            float4 a = Ya[idx], b = Yb[idx];
            float4 o; o.x = a.x + b.x; o.y = a.y + b.y; o.z = a.z + b.z; o.w = a.w + b.w;
            ysv[idx] = o;
        }
    }
    if (tid < 128) {
        const float* p = XYZ + (node0 + tid) * 3;
        xyzs[tid * 4 + 0] = p[0];
        xyzs[tid * 4 + 1] = p[1];
        xyzs[tid * 4 + 2] = p[2];
        xyzs[tid * 4 + 3] = 0.f;
    }
    __syncthreads();

    // precompute w matrix: ws[j*64 + i] = exp(-dist(i0+i, j)); diag -> w=1
    #pragma unroll
    for (int t = 0; t < 8; t++) {
        int idx = tid + t * 1024;
        int ii = idx & 63;
        int jj = idx >> 6;
        float dx = xyzs[((i0 + ii) << 2) + 0] - xyzs[(jj << 2) + 0];
        float dy = xyzs[((i0 + ii) << 2) + 1] - xyzs[(jj << 2) + 1];
        float dz = xyzs[((i0 + ii) << 2) + 2] - xyzs[(jj << 2) + 2];
        float d2 = dx * dx + dy * dy + dz * dz;
        float dist = d2 * rsqrt_ap(fmaxf(d2, 1e-30f));   // sqrt(d2)
        ws[(jj << 6) + ii] = ex2_ap(-dist * LOG2E);      // exp(-dist)
    }

    // cache y_i (two rows) and b1 as packed pairs (2 ull = 4 floats each)
    ull yiA[2], yiB[2], b1p[2];
    {
        const ull* b1u = (const ull*)b1;
        b1p[0] = b1u[lane * 2 + 0];
        b1p[1] = b1u[lane * 2 + 1];
    }
    __syncthreads();      // ws ready; ys ready
    {
        const ull* ysu = (const ull*)ys;
        int offA = (i0 + iA) * 64 + lane * 2;
        int offB = (i0 + iB) * 64 + lane * 2;
        yiA[0] = ysu[offA]; yiA[1] = ysu[offA + 1];
        yiB[0] = ysu[offB]; yiB[1] = ysu[offB + 1];
    }
    ull accA[2] = {0ULL, 0ULL}, accB[2] = {0ULL, 0ULL};

    // ---- main pairwise loop over j ----
    #pragma unroll 4
    for (int j = 0; j < 128; j++) {
        ull wv = *(const ull*)(ws + (j << 6) + iA);
        float w0, w1;
        unpack2(wv, w0, w1);
        ull w20 = pack2(w0, w0);
        ull w21 = pack2(w1, w1);
        ulonglong2 yj = *(const ulonglong2*)(ys + (j << 7) + dbase);
        ull yjp[2] = {yj.x, yj.y};
        #pragma unroll
        for (int p = 0; p < 2; p++) {
            ull dfA = fma2(yjp[p], NEG1_2, yiA[p]);
            ull tA  = fma2(w20, dfA, b1p[p]);
            float lo, hi;
            unpack2(tA, lo, hi);
            lo = fmaxf(lo, 0.f); hi = fmaxf(hi, 0.f);
            accA[p] = add2(accA[p], pack2(lo, hi));

            ull dfB = fma2(yjp[p], NEG1_2, yiB[p]);
            ull tB  = fma2(w21, dfB, b1p[p]);
            unpack2(tB, lo, hi);
            lo = fmaxf(lo, 0.f); hi = fmaxf(hi, 0.f);
            accB[p] = add2(accB[p], pack2(lo, hi));
        }
    }

    // ---- epilogue: self-edge correction + warp-shuffle LayerNorm + fused BN ----
    float afA[4], afB[4];
    #pragma unroll
    for (int p = 0; p < 2; p++) {
        float bl, bh; unpack2(b1p[p], bl, bh);
        float rb0 = fmaxf(bl, 0.f), rb1 = fmaxf(bh, 0.f);
        float lo, hi;
        unpack2(accA[p], lo, hi);
        afA[2 * p + 0] = lo - rb0;
        afA[2 * p + 1] = hi - rb1;
        unpack2(accB[p], lo, hi);
        afB[2 * p + 0] = lo - rb0;
        afB[2 * p + 1] = hi - rb1;
    }
    float sA = 0.f, qA = 0.f, sB = 0.f, qB = 0.f;
    #pragma unroll
    for (int k = 0; k < 4; k++) {
        sA += afA[k]; qA += afA[k] * afA[k];
        sB += afB[k]; qB += afB[k] * afB[k];
    }
    #pragma unroll
    for (int off = 16; off > 0; off >>= 1) {
        sA += __shfl_xor_sync(0xffffffffu, sA, off);
        qA += __shfl_xor_sync(0xffffffffu, qA, off);
        sB += __shfl_xor_sync(0xffffffffu, sB, off);
        qB += __shfl_xor_sync(0xffffffffu, qB, off);
    }
    float muA  = sA * (1.f / 128.f);
    float invA = 1.f / sqrtf(qA * (1.f / 128.f) - muA * muA + EPSV);
    float muB  = sB * (1.f / 128.f);
    float invB = 1.f / sqrtf(qB * (1.f / 128.f) - muB * muB + EPSV);

    float4 gv = *(const float4*)(ln_g + dbase);
    float4 bv = *(const float4*)(ln_b + dbase);
    float4 sc = *(const float4*)(g_bstats + dbase);
    float4 sh = *(const float4*)(g_bstats + 128 + dbase);

    int gbA = ((node0 + i0 + iA) << 7) + dbase;
    int gbB = ((node0 + i0 + iB) << 7) + dbase;
    {
        float4 xv = *(const float4*)(X + gbA);
        float4 pv = *(const float4*)(g_P2 + gbA);
        float4 o;
        o.x = xv.x + (afA[0] - muA) * invA * gv.x + bv.x + pv.x * sc.x + sh.x;
        o.y = xv.y + (afA[1] - muA) * invA * gv.y + bv.y + pv.y * sc.y + sh.y;
        o.z = xv.z + (afA[2] - muA) * invA * gv.z + bv.z + pv.z * sc.z + sh.z;
        o.w = xv.w + (afA[3] - muA) * invA * gv.w + bv.w + pv.w * sc.w + sh.w;
        *(float4*)(out + gbA) = o;
    }
    {
        float4 xv = *(const float4*)(X + gbB);
        float4 pv = *(const float4*)(g_P2 + gbB);
        float4 o;
        o.x = xv.x + (afB[0] - muB) * invB * gv.x + bv.x + pv.x * sc.x + sh.x;
        o.y = xv.y + (afB[1] - muB) * invB * gv.y + bv.y + pv.y * sc.y + sh.y;
        o.z = xv.z + (afB[2] - muB) * invB * gv.z + bv.z + pv.z * sc.z + sh.z;
        o.w = xv.w + (afB[3] - muB) * invB * gv.w + bv.w + pv.w * sc.w + sh.w;
        *(float4*)(out + gbB) = o;
    }
}

// ============================================================================
extern "C" void kernel_launch(void* const* d_in, const int* in_sizes, int n_in,
                              void* d_out, int out_size) {
    const float* X    = (const float*)d_in[0];
    const float* XYZ  = (const float*)d_in[1];
    const float* Wxyz = (const float*)d_in[2];
    const float* bn_g = (const float*)d_in[3];
    const float* bn_b = (const float*)d_in[4];
    const float* W1   = (const float*)d_in[5];
    const float* b1   = (const float*)d_in[6];
    const float* ln_g = (const float*)d_in[7];
    const float* ln_b = (const float*)d_in[8];
    float* out = (float*)d_out;

    const int smem0 = 12288 * 8;                               // 96 KB
    const int smem1 = (16384 + 8192 + 512) * 4;                // ~100.4 KB
    const int smem2 = (16384 + 8448 + 512 + 384) * 4;          // ~102.9 KB

    cudaFuncSetAttribute(k0_gemm,    cudaFuncAttributeMaxDynamicSharedMemorySize, smem0);
    cudaFuncSetAttribute(k1_branch1, cudaFuncAttributeMaxDynamicSharedMemorySize, smem1);
    cudaFuncSetAttribute(k2_branch2, cudaFuncAttributeMaxDynamicSharedMemorySize, smem2);

    // Fork-join: k0 (legacy stream) runs concurrently with k2 (forked stream).
    // Stream/events are intentionally NOT destroyed here (capture safety).
    cudaStream_t s1;
    cudaStreamCreateWithFlags(&s1, cudaStreamNonBlocking);
    cudaEvent_t evA, evB;
    cudaEventCreateWithFlags(&evA, cudaEventDisableTiming);
    cudaEventCreateWithFlags(&evB, cudaEventDisableTiming);

    cudaEventRecord(evA, 0);
    cudaStreamWaitEvent(s1, evA, 0);

    k0_gemm   <<<128, 256, smem0>>>(X, W1);                     // legacy stream
    k2_branch2<<<128, 512, smem2, s1>>>(XYZ, Wxyz, bn_g, bn_b); // forked stream

    cudaEventRecord(evB, s1);
    cudaStreamWaitEvent(0, evB, 0);

    k1_branch1<<<128, 1024, smem1>>>(X, XYZ, b1, ln_g, ln_b, out);
}